// round 6
// baseline (speedup 1.0000x reference)
#include <cuda_runtime.h>
#include <cstdint>

// ============================================================================
// Problem sizes / tiling
// ============================================================================
#define MM 8192
#define NN 16384
#define KK 4096
#define BM 128
#define BN 128
#define BK 64
#define STAGES 4
#define KTILES (KK / BK)        // 64
#define ROWB 80                 // padded SMEM row: 64 data bytes + 16 pad
#define ATILE (BM * ROWB)       // 10240 bytes per tile array
#define STAGE_BYTES (3 * ATILE) // Aa + Ab + W tiles = 30720
#define SMEM_BYTES (STAGES * STAGE_BYTES)  // 122880

// Scratch (allocation-free rule: __device__ globals)
static __device__ __align__(1024) int8_t g_Aa[(size_t)MM * KK];  // 32 MB  hi int8 of x
static __device__ __align__(1024) int8_t g_Ab[(size_t)MM * KK];  // 32 MB  lo int8 of x
static __device__ __align__(1024) int8_t g_W[(size_t)NN * KK];   // 64 MB  repacked weights
static __device__ float g_s[MM];                                 // per-row scale of x

// ============================================================================
// PTX helpers (plain sm_103-safe)
// ============================================================================
__device__ __forceinline__ uint32_t smem_to_u32(const void* p) {
    uint32_t a;
    asm("{ .reg .u64 t; cvta.to.shared.u64 t, %1; cvt.u32.u64 %0, t; }" : "=r"(a) : "l"(p));
    return a;
}

__device__ __forceinline__ void cp16(uint32_t dst, const void* src) {
    asm volatile("cp.async.cg.shared.global [%0], [%1], 16;" :: "r"(dst), "l"(src));
}
#define CP_COMMIT() asm volatile("cp.async.commit_group;" ::: "memory")
#define CP_WAIT(n)  asm volatile("cp.async.wait_group %0;" :: "n"(n) : "memory")

__device__ __forceinline__ uint32_t lds32(uint32_t a) {
    uint32_t v;
    asm volatile("ld.shared.b32 %0, [%1];" : "=r"(v) : "r"(a));
    return v;
}

// D(s32) += A(s8,row) * B(s8,col);  m16n8k32
__device__ __forceinline__ void mma_s8(int* d, const uint32_t* a, uint32_t b0, uint32_t b1) {
    asm volatile(
        "mma.sync.aligned.m16n8k32.row.col.s32.s8.s8.s32 "
        "{%0,%1,%2,%3}, {%4,%5,%6,%7}, {%8,%9}, {%0,%1,%2,%3};"
        : "+r"(d[0]), "+r"(d[1]), "+r"(d[2]), "+r"(d[3])
        : "r"(a[0]), "r"(a[1]), "r"(a[2]), "r"(a[3]), "r"(b0), "r"(b1));
}

// ============================================================================
// W repack: harness stores the int8 weight tensor as int32 (per the harness
// dtype contract: float32/int32/bfloat16 only). Take low byte of each int32.
// Each thread: 16 int32 (64B) -> 16 bytes.
// ============================================================================
__global__ void __launch_bounds__(256) k_wpack(const int4* __restrict__ w32) {
    size_t i = (size_t)blockIdx.x * blockDim.x + threadIdx.x;   // 0 .. 4194303
    int4 v0 = w32[i * 4 + 0];
    int4 v1 = w32[i * 4 + 1];
    int4 v2 = w32[i * 4 + 2];
    int4 v3 = w32[i * 4 + 3];
    uint32_t p0 = (v0.x & 0xFF) | ((v0.y & 0xFF) << 8) | ((v0.z & 0xFF) << 16) | ((uint32_t)(v0.w & 0xFF) << 24);
    uint32_t p1 = (v1.x & 0xFF) | ((v1.y & 0xFF) << 8) | ((v1.z & 0xFF) << 16) | ((uint32_t)(v1.w & 0xFF) << 24);
    uint32_t p2 = (v2.x & 0xFF) | ((v2.y & 0xFF) << 8) | ((v2.z & 0xFF) << 16) | ((uint32_t)(v2.w & 0xFF) << 24);
    uint32_t p3 = (v3.x & 0xFF) | ((v3.y & 0xFF) << 8) | ((v3.z & 0xFF) << 16) | ((uint32_t)(v3.w & 0xFF) << 24);
    *(uint4*)(g_W + i * 16) = make_uint4(p0, p1, p2, p3);
}

// ============================================================================
// Quantization: x[row] -> s_row, a8 (hi), b8 (lo);  x ~= s_row * (a*128 + b)
// ============================================================================
__global__ void __launch_bounds__(256) k_quant(const float4* __restrict__ x) {
    int row = blockIdx.x;
    int t = threadIdx.x;
    const float4* xr = x + (size_t)row * (KK / 4);

    float4 v[4];
    float mx = 0.f;
#pragma unroll
    for (int j = 0; j < 4; j++) {
        v[j] = xr[t * 4 + j];
        mx = fmaxf(mx, fmaxf(fmaxf(fabsf(v[j].x), fabsf(v[j].y)),
                             fmaxf(fabsf(v[j].z), fabsf(v[j].w))));
    }
    __shared__ float red[8];
#pragma unroll
    for (int o = 16; o; o >>= 1) mx = fmaxf(mx, __shfl_xor_sync(~0u, mx, o));
    if ((t & 31) == 0) red[t >> 5] = mx;
    __syncthreads();
    float m = red[0];
#pragma unroll
    for (int i = 1; i < 8; i++) m = fmaxf(m, red[i]);

    float inv = (m > 0.f) ? 16256.f / m : 0.f;
    if (t == 0) g_s[row] = m * (1.f / 16256.f);

    uint32_t pa[4], pb[4];
#pragma unroll
    for (int j = 0; j < 4; j++) {
        float fv[4] = {v[j].x, v[j].y, v[j].z, v[j].w};
        uint32_t wa = 0, wb = 0;
#pragma unroll
        for (int e = 0; e < 4; e++) {
            int q = __float2int_rn(fv[e] * inv);   // |q| <= 16256
            int a = (q + 64) >> 7;                 // a in [-127,127]
            int b = q - (a << 7);                  // b in [-64,63]; q == 128a + b exact
            wa |= ((uint32_t)(uint8_t)(int8_t)a) << (8 * e);
            wb |= ((uint32_t)(uint8_t)(int8_t)b) << (8 * e);
        }
        pa[j] = wa; pb[j] = wb;
    }
    size_t base = (size_t)row * KK + (size_t)t * 16;
    *(uint4*)(g_Aa + base) = make_uint4(pa[0], pa[1], pa[2], pa[3]);
    *(uint4*)(g_Ab + base) = make_uint4(pb[0], pb[1], pb[2], pb[3]);
}

// ============================================================================
// GEMM: Sa = Aa @ W^T, Sb = Ab @ W^T  (int32, exact)
// out = s_row * scale_n * (128*Sa + Sb) + bias_n
// Block 128x128, 8 warps (4m x 2n), warp tile 32x64, BK=64, 4-stage cp.async.
// Fragment loads: per-lane ld.shared.b32 at exact PTX-ISA fragment coords.
// ============================================================================
__global__ void __launch_bounds__(256, 1) gemm_kernel(
    const float* __restrict__ scale,   // [NN]
    const float* __restrict__ bias,    // [NN]
    float* __restrict__ out)           // [MM][NN]
{
    extern __shared__ char smem[];
    uint32_t sb = smem_to_u32(smem);
    int tid = threadIdx.x;

    // L2-friendly tile order: groups of 8 m-tiles sweep n
    const int ntm = MM / BM, ntn = NN / BN;   // 64, 128
    const int GROUPM = 8;
    int pid = blockIdx.x;
    int npg = GROUPM * ntn;
    int gid = pid / npg;
    int fm = gid * GROUPM;
    int gsz = (ntm - fm < GROUPM) ? (ntm - fm) : GROUPM;
    int tm = fm + (pid % gsz);
    int tn = (pid % npg) / gsz;
    int m0 = tm * BM, n0 = tn * BN;

    // ---- stage loader: 1536 x 16B chunks / 256 threads = 6 per thread ----
    auto load_stage = [&](int slot, int kt) {
        uint32_t sbase = sb + slot * STAGE_BYTES;
        int k0 = kt * BK;
#pragma unroll
        for (int i = 0; i < 6; i++) {
            int c = tid + i * 256;           // 0..1535
            int arr = c >> 9;                // 0:Aa 1:Ab 2:W
            int idx = c & 511;
            int row = idx >> 2, ch = idx & 3;
            uint32_t dst = sbase + arr * ATILE + row * ROWB + ch * 16;
            const int8_t* src;
            if (arr == 0)      src = g_Aa + (size_t)(m0 + row) * KK + k0 + ch * 16;
            else if (arr == 1) src = g_Ab + (size_t)(m0 + row) * KK + k0 + ch * 16;
            else               src = g_W  + (size_t)(n0 + row) * KK + k0 + ch * 16;
            cp16(dst, src);
        }
    };

    int w = tid >> 5, lane = tid & 31;
    int mw = w >> 1, nw = w & 1;             // warp grid 4m x 2n
    int g = lane >> 2, q = lane & 3;         // PTX: groupID, threadID_in_group

    int accA[2][8][4] = {};
    int accB[2][8][4] = {};

    // ---- prologue ----
#pragma unroll
    for (int s = 0; s < STAGES - 1; s++) { load_stage(s, s); CP_COMMIT(); }

    // ---- mainloop ----
    for (int kt = 0; kt < KTILES; kt++) {
        CP_WAIT(STAGES - 2);
        __syncthreads();
        if (kt + STAGES - 1 < KTILES) load_stage((kt + STAGES - 1) % STAGES, kt + STAGES - 1);
        CP_COMMIT();

        uint32_t sbase = sb + (kt % STAGES) * STAGE_BYTES;
#pragma unroll
        for (int ks = 0; ks < 2; ks++) {
            // A fragments per PTX ISA m16n8k32.s8 table:
            // a0:(row g, bytes 4q) a1:(g+8, 4q) a2:(g, 16+4q) a3:(g+8, 16+4q)
            uint32_t fa[2][4], fb[2][4];
#pragma unroll
            for (int mf = 0; mf < 2; mf++) {
                uint32_t r0 = sbase + (uint32_t)(mw * 32 + mf * 16 + g) * ROWB + ks * 32 + q * 4;
                uint32_t r1 = r0 + 8 * ROWB;
                fa[mf][0] = lds32(r0);
                fa[mf][1] = lds32(r1);
                fa[mf][2] = lds32(r0 + 16);
                fa[mf][3] = lds32(r1 + 16);
                fb[mf][0] = lds32(r0 + ATILE);
                fb[mf][1] = lds32(r1 + ATILE);
                fb[mf][2] = lds32(r0 + ATILE + 16);
                fb[mf][3] = lds32(r1 + ATILE + 16);
            }
#pragma unroll
            for (int nf = 0; nf < 8; nf++) {
                // B per PTX ISA: b0:(col g, bytes 4q)  b1:(col g, 16+4q)
                uint32_t nb = sbase + 2 * ATILE +
                              (uint32_t)(nw * 64 + nf * 8 + g) * ROWB + ks * 32 + q * 4;
                uint32_t b0 = lds32(nb);
                uint32_t b1 = lds32(nb + 16);
#pragma unroll
                for (int mf = 0; mf < 2; mf++) {
                    mma_s8(accA[mf][nf], fa[mf], b0, b1);
                    mma_s8(accB[mf][nf], fb[mf], b0, b1);
                }
            }
        }
    }

    // ---- epilogue: out = s_row * scale_n * (128*Sa + Sb) + bias_n ----
    // C frag: c0:(g, 2q) c1:(g, 2q+1) c2:(g+8, 2q) c3:(g+8, 2q+1)
#pragma unroll
    for (int mf = 0; mf < 2; mf++) {
        int r0 = m0 + mw * 32 + mf * 16 + g;
        float s0 = g_s[r0], s1 = g_s[r0 + 8];
#pragma unroll
        for (int nf = 0; nf < 8; nf++) {
            int c = n0 + nw * 64 + nf * 8 + q * 2;
            float sc0 = __ldg(scale + c), sc1 = __ldg(scale + c + 1);
            float bb0 = __ldg(bias + c),  bb1 = __ldg(bias + c + 1);
            const int* da = accA[mf][nf];
            const int* db = accB[mf][nf];
            float f00 = fmaf(128.f, (float)da[0], (float)db[0]);
            float f01 = fmaf(128.f, (float)da[1], (float)db[1]);
            float f10 = fmaf(128.f, (float)da[2], (float)db[2]);
            float f11 = fmaf(128.f, (float)da[3], (float)db[3]);
            float2 v0 = make_float2(f00 * (s0 * sc0) + bb0, f01 * (s0 * sc1) + bb1);
            float2 v1 = make_float2(f10 * (s1 * sc0) + bb0, f11 * (s1 * sc1) + bb1);
            *(float2*)(out + (size_t)r0 * NN + c)       = v0;
            *(float2*)(out + (size_t)(r0 + 8) * NN + c) = v1;
        }
    }
}

// ============================================================================
// Host side — inputs identified by element count
// x: 33554432 f32 | W: 67108864 int32 (harness stores int8 as int32)
// scale, bias: 16384 f32 each, in metadata order
// ============================================================================
extern "C" void kernel_launch(void* const* d_in, const int* in_sizes, int n_in,
                              void* d_out, int out_size) {
    const float*   x     = nullptr;
    const int32_t* w32   = nullptr;
    const float*   scale = nullptr;
    const float*   bias  = nullptr;
    for (int i = 0; i < n_in; i++) {
        if (in_sizes[i] == MM * KK)           x   = (const float*)d_in[i];
        else if (in_sizes[i] == NN * KK)      w32 = (const int32_t*)d_in[i];
        else if (in_sizes[i] == NN) {
            if (!scale) scale = (const float*)d_in[i];
            else        bias  = (const float*)d_in[i];
        }
    }
    float* out = (float*)d_out;

    cudaFuncSetAttribute(gemm_kernel, cudaFuncAttributeMaxDynamicSharedMemorySize, SMEM_BYTES);

    k_wpack<<<(NN * (size_t)KK) / (16 * 256), 256>>>((const int4*)w32);
    k_quant<<<MM, 256>>>((const float4*)x);
    gemm_kernel<<<(MM / BM) * (NN / BN), 256, SMEM_BYTES>>>(scale, bias, out);
}

// round 8
// speedup vs baseline: 1.0563x; 1.0563x over previous
#include <cuda_runtime.h>
#include <cstdint>

// ============================================================================
// Problem sizes / tiling
// ============================================================================
#define MM 8192
#define NN 16384
#define KK 4096
#define BM 128
#define BN 128
#define BK 64
#define STAGES 4
#define KTILES (KK / BK)        // 64
#define ROWB 80                 // padded SMEM row: 64 data bytes + 16 pad (conflict-free)
#define ATILE (BM * ROWB)       // 10240 bytes per tile array
#define STAGE_BYTES (3 * ATILE) // Aa + Ab + W tiles = 30720
#define SMEM_BYTES (STAGES * STAGE_BYTES)  // 122880
#define NTHREADS 512

// Scratch (allocation-free rule: __device__ globals)
static __device__ __align__(1024) int8_t g_Aa[(size_t)MM * KK];  // 32 MB  hi int8 of x
static __device__ __align__(1024) int8_t g_Ab[(size_t)MM * KK];  // 32 MB  lo int8 of x
static __device__ __align__(1024) int8_t g_W[(size_t)NN * KK];   // 64 MB  repacked weights
static __device__ float g_s[MM];                                 // per-row scale of x

// ============================================================================
// PTX helpers (plain sm_103-safe)
// ============================================================================
__device__ __forceinline__ uint32_t smem_to_u32(const void* p) {
    uint32_t a;
    asm("{ .reg .u64 t; cvta.to.shared.u64 t, %1; cvt.u32.u64 %0, t; }" : "=r"(a) : "l"(p));
    return a;
}

__device__ __forceinline__ void cp16(uint32_t dst, const void* src) {
    asm volatile("cp.async.cg.shared.global [%0], [%1], 16;" :: "r"(dst), "l"(src));
}
#define CP_COMMIT() asm volatile("cp.async.commit_group;" ::: "memory")
#define CP_WAIT(n)  asm volatile("cp.async.wait_group %0;" :: "n"(n) : "memory")

__device__ __forceinline__ void ldm4(uint32_t* r, uint32_t addr) {
    asm volatile("ldmatrix.sync.aligned.m8n8.x4.shared.b16 {%0,%1,%2,%3}, [%4];"
        : "=r"(r[0]), "=r"(r[1]), "=r"(r[2]), "=r"(r[3]) : "r"(addr));
}

// D(s32) += A(s8,row) * B(s8,col);  m16n8k32
__device__ __forceinline__ void mma_s8(int* d, const uint32_t* a, uint32_t b0, uint32_t b1) {
    asm volatile(
        "mma.sync.aligned.m16n8k32.row.col.s32.s8.s8.s32 "
        "{%0,%1,%2,%3}, {%4,%5,%6,%7}, {%8,%9}, {%0,%1,%2,%3};"
        : "+r"(d[0]), "+r"(d[1]), "+r"(d[2]), "+r"(d[3])
        : "r"(a[0]), "r"(a[1]), "r"(a[2]), "r"(a[3]), "r"(b0), "r"(b1));
}

// ============================================================================
// W repack: harness stores the int8 weight tensor as int32. Low byte of each.
// ============================================================================
__global__ void __launch_bounds__(256) k_wpack(const int4* __restrict__ w32) {
    size_t i = (size_t)blockIdx.x * blockDim.x + threadIdx.x;
    int4 v0 = w32[i * 4 + 0];
    int4 v1 = w32[i * 4 + 1];
    int4 v2 = w32[i * 4 + 2];
    int4 v3 = w32[i * 4 + 3];
    uint32_t p0 = (v0.x & 0xFF) | ((v0.y & 0xFF) << 8) | ((v0.z & 0xFF) << 16) | ((uint32_t)(v0.w & 0xFF) << 24);
    uint32_t p1 = (v1.x & 0xFF) | ((v1.y & 0xFF) << 8) | ((v1.z & 0xFF) << 16) | ((uint32_t)(v1.w & 0xFF) << 24);
    uint32_t p2 = (v2.x & 0xFF) | ((v2.y & 0xFF) << 8) | ((v2.z & 0xFF) << 16) | ((uint32_t)(v2.w & 0xFF) << 24);
    uint32_t p3 = (v3.x & 0xFF) | ((v3.y & 0xFF) << 8) | ((v3.z & 0xFF) << 16) | ((uint32_t)(v3.w & 0xFF) << 24);
    *(uint4*)(g_W + i * 16) = make_uint4(p0, p1, p2, p3);
}

// ============================================================================
// Quantization: x[row] -> s_row, a8 (hi), b8 (lo);  x ~= s_row * (a*128 + b)
// ============================================================================
__global__ void __launch_bounds__(256) k_quant(const float4* __restrict__ x) {
    int row = blockIdx.x;
    int t = threadIdx.x;
    const float4* xr = x + (size_t)row * (KK / 4);

    float4 v[4];
    float mx = 0.f;
#pragma unroll
    for (int j = 0; j < 4; j++) {
        v[j] = xr[t * 4 + j];
        mx = fmaxf(mx, fmaxf(fmaxf(fabsf(v[j].x), fabsf(v[j].y)),
                             fmaxf(fabsf(v[j].z), fabsf(v[j].w))));
    }
    __shared__ float red[8];
#pragma unroll
    for (int o = 16; o; o >>= 1) mx = fmaxf(mx, __shfl_xor_sync(~0u, mx, o));
    if ((t & 31) == 0) red[t >> 5] = mx;
    __syncthreads();
    float m = red[0];
#pragma unroll
    for (int i = 1; i < 8; i++) m = fmaxf(m, red[i]);

    float inv = (m > 0.f) ? 16256.f / m : 0.f;
    if (t == 0) g_s[row] = m * (1.f / 16256.f);

    uint32_t pa[4], pb[4];
#pragma unroll
    for (int j = 0; j < 4; j++) {
        float fv[4] = {v[j].x, v[j].y, v[j].z, v[j].w};
        uint32_t wa = 0, wb = 0;
#pragma unroll
        for (int e = 0; e < 4; e++) {
            int q = __float2int_rn(fv[e] * inv);   // |q| <= 16256
            int a = (q + 64) >> 7;                 // a in [-127,127]
            int b = q - (a << 7);                  // b in [-64,63]; q == 128a + b exact
            wa |= ((uint32_t)(uint8_t)(int8_t)a) << (8 * e);
            wb |= ((uint32_t)(uint8_t)(int8_t)b) << (8 * e);
        }
        pa[j] = wa; pb[j] = wb;
    }
    size_t base = (size_t)row * KK + (size_t)t * 16;
    *(uint4*)(g_Aa + base) = make_uint4(pa[0], pa[1], pa[2], pa[3]);
    *(uint4*)(g_Ab + base) = make_uint4(pb[0], pb[1], pb[2], pb[3]);
}

// ============================================================================
// GEMM: Sa = Aa @ W^T, Sb = Ab @ W^T  (int32, exact)
// out = s_row * scale_n * (128*Sa + Sb) + bias_n
// Block 128x128, 16 warps (4m x 4n), warp tile 32x32, BK=64, 4-stage cp.async.
// Fragments via ldmatrix.x4 (choreography empirically equivalent to the
// passing explicit-table version: R2 == R3 outputs, R3/R6 dataflow passes).
// ============================================================================
__global__ void __launch_bounds__(NTHREADS, 1) gemm_kernel(
    const float* __restrict__ scale,   // [NN]
    const float* __restrict__ bias,    // [NN]
    float* __restrict__ out)           // [MM][NN]
{
    extern __shared__ char smem[];
    uint32_t sb = smem_to_u32(smem);
    int tid = threadIdx.x;

    // L2-friendly tile order: groups of 8 m-tiles sweep n
    const int ntm = MM / BM, ntn = NN / BN;   // 64, 128
    const int GROUPM = 8;
    int pid = blockIdx.x;
    int npg = GROUPM * ntn;
    int gid = pid / npg;
    int fm = gid * GROUPM;
    int gsz = (ntm - fm < GROUPM) ? (ntm - fm) : GROUPM;
    int tm = fm + (pid % gsz);
    int tn = (pid % npg) / gsz;
    int m0 = tm * BM, n0 = tn * BN;

    // ---- stage loader: 1536 x 16B chunks / 512 threads = 3 per thread ----
    auto load_stage = [&](int slot, int kt) {
        uint32_t sbase = sb + slot * STAGE_BYTES;
        int k0 = kt * BK;
#pragma unroll
        for (int i = 0; i < 3; i++) {
            int c = tid + i * NTHREADS;      // 0..1535
            int arr = c >> 9;                // 0:Aa 1:Ab 2:W
            int idx = c & 511;
            int row = idx >> 2, ch = idx & 3;
            uint32_t dst = sbase + arr * ATILE + row * ROWB + ch * 16;
            const int8_t* src;
            if (arr == 0)      src = g_Aa + (size_t)(m0 + row) * KK + k0 + ch * 16;
            else if (arr == 1) src = g_Ab + (size_t)(m0 + row) * KK + k0 + ch * 16;
            else               src = g_W  + (size_t)(n0 + row) * KK + k0 + ch * 16;
            cp16(dst, src);
        }
    };

    int w = tid >> 5, lane = tid & 31;
    int mw = w >> 2, nw = w & 3;             // warp grid 4m x 4n, warp tile 32x32
    int r = lane & 7, seg = lane >> 3;
    int g = lane >> 2, q = lane & 3;         // C-fragment coords

    // ldmatrix source offsets (stage-independent parts)
    // A (m16k32): lanes 0-7 rows+0 klo | 8-15 +8 klo | 16-23 +0 khi | 24-31 +8 khi
    uint32_t aoff[2];
#pragma unroll
    for (int mf = 0; mf < 2; mf++) {
        int arow = mw * 32 + mf * 16 + r + (seg & 1) * 8;
        aoff[mf] = (uint32_t)arow * ROWB + (seg >> 1) * 16;
    }
    // B pair p covers n8-frags 2p,2p+1:
    // lanes 0-7 rows+0 klo | 8-15 +0 khi | 16-23 +8 klo | 24-31 +8 khi
    uint32_t boff[2];
#pragma unroll
    for (int p = 0; p < 2; p++) {
        int brow = nw * 32 + p * 16 + r + (seg >> 1) * 8;
        boff[p] = 2 * ATILE + (uint32_t)brow * ROWB + (seg & 1) * 16;
    }

    int accA[2][4][4] = {};   // hi GEMM  [m16 frag][n8 frag][c0..c3]
    int accB[2][4][4] = {};   // lo GEMM

    // ---- prologue ----
#pragma unroll
    for (int s = 0; s < STAGES - 1; s++) { load_stage(s, s); CP_COMMIT(); }

    // ---- mainloop ----
    for (int kt = 0; kt < KTILES; kt++) {
        CP_WAIT(STAGES - 2);
        __syncthreads();
        if (kt + STAGES - 1 < KTILES) load_stage((kt + STAGES - 1) % STAGES, kt + STAGES - 1);
        CP_COMMIT();

        uint32_t sbase = sb + (kt % STAGES) * STAGE_BYTES;
#pragma unroll
        for (int ks = 0; ks < 2; ks++) {
            uint32_t fa[2][4], fb[2][4], fB[2][4];
#pragma unroll
            for (int mf = 0; mf < 2; mf++) {
                ldm4(fa[mf], sbase + aoff[mf] + ks * 32);
                ldm4(fb[mf], sbase + ATILE + aoff[mf] + ks * 32);
            }
#pragma unroll
            for (int p = 0; p < 2; p++) ldm4(fB[p], sbase + boff[p] + ks * 32);
#pragma unroll
            for (int mf = 0; mf < 2; mf++) {
#pragma unroll
                for (int nf = 0; nf < 4; nf++) {
                    uint32_t b0 = fB[nf >> 1][(nf & 1) * 2];
                    uint32_t b1 = fB[nf >> 1][(nf & 1) * 2 + 1];
                    mma_s8(accA[mf][nf], fa[mf], b0, b1);
                    mma_s8(accB[mf][nf], fb[mf], b0, b1);
                }
            }
        }
    }

    // ---- epilogue: out = s_row * scale_n * (128*Sa + Sb) + bias_n ----
    // C frag: c0:(g, 2q) c1:(g, 2q+1) c2:(g+8, 2q) c3:(g+8, 2q+1)
#pragma unroll
    for (int mf = 0; mf < 2; mf++) {
        int r0 = m0 + mw * 32 + mf * 16 + g;
        float s0 = g_s[r0], s1 = g_s[r0 + 8];
#pragma unroll
        for (int nf = 0; nf < 4; nf++) {
            int c = n0 + nw * 32 + nf * 8 + q * 2;
            float sc0 = __ldg(scale + c), sc1 = __ldg(scale + c + 1);
            float bb0 = __ldg(bias + c),  bb1 = __ldg(bias + c + 1);
            const int* da = accA[mf][nf];
            const int* db = accB[mf][nf];
            float f00 = fmaf(128.f, (float)da[0], (float)db[0]);
            float f01 = fmaf(128.f, (float)da[1], (float)db[1]);
            float f10 = fmaf(128.f, (float)da[2], (float)db[2]);
            float f11 = fmaf(128.f, (float)da[3], (float)db[3]);
            float2 v0 = make_float2(f00 * (s0 * sc0) + bb0, f01 * (s0 * sc1) + bb1);
            float2 v1 = make_float2(f10 * (s1 * sc0) + bb0, f11 * (s1 * sc1) + bb1);
            *(float2*)(out + (size_t)r0 * NN + c)       = v0;
            *(float2*)(out + (size_t)(r0 + 8) * NN + c) = v1;
        }
    }
}

// ============================================================================
// Host side — inputs identified by element count
// ============================================================================
extern "C" void kernel_launch(void* const* d_in, const int* in_sizes, int n_in,
                              void* d_out, int out_size) {
    const float*   x     = nullptr;
    const int32_t* w32   = nullptr;
    const float*   scale = nullptr;
    const float*   bias  = nullptr;
    for (int i = 0; i < n_in; i++) {
        if (in_sizes[i] == MM * KK)           x   = (const float*)d_in[i];
        else if (in_sizes[i] == NN * KK)      w32 = (const int32_t*)d_in[i];
        else if (in_sizes[i] == NN) {
            if (!scale) scale = (const float*)d_in[i];
            else        bias  = (const float*)d_in[i];
        }
    }
    float* out = (float*)d_out;

    cudaFuncSetAttribute(gemm_kernel, cudaFuncAttributeMaxDynamicSharedMemorySize, SMEM_BYTES);

    k_wpack<<<(NN * (size_t)KK) / (16 * 256), 256>>>((const int4*)w32);
    k_quant<<<MM, 256>>>((const float4*)x);
    gemm_kernel<<<(MM / BM) * (NN / BN), NTHREADS, SMEM_BYTES>>>(scale, bias, out);
}

// round 10
// speedup vs baseline: 2.5562x; 2.4200x over previous
#include <cuda_runtime.h>
#include <cuda_bf16.h>
#include <cstdint>

// ============================================================================
// Problem sizes / tiling
// ============================================================================
#define MM 8192
#define NN 16384
#define KK 4096
#define BM 128
#define BN 128
#define BKB 64                  // K-bytes per stage tile = 32 bf16 elements
#define STAGES 4
#define KTILES (KK * 2 / BKB)   // 128
#define ROWB 80                 // padded SMEM row: 64 data bytes + 16 pad (conflict-free)
#define ATILE (BM * ROWB)       // 10240 bytes per tile array
#define STAGE_BYTES (3 * ATILE) // Ahi + Alo + W tiles = 30720
#define SMEM_BYTES (STAGES * STAGE_BYTES)  // 122880
#define NTHREADS 512

// Scratch (allocation-free rule: __device__ globals)
static __device__ __align__(1024) __nv_bfloat16 g_Ahi[(size_t)MM * KK]; // 64 MB
static __device__ __align__(1024) __nv_bfloat16 g_Alo[(size_t)MM * KK]; // 64 MB
static __device__ __align__(1024) __nv_bfloat16 g_Wb[(size_t)NN * KK];  // 128 MB

// ============================================================================
// PTX helpers (plain sm_103-safe)
// ============================================================================
__device__ __forceinline__ uint32_t smem_to_u32(const void* p) {
    uint32_t a;
    asm("{ .reg .u64 t; cvta.to.shared.u64 t, %1; cvt.u32.u64 %0, t; }" : "=r"(a) : "l"(p));
    return a;
}

__device__ __forceinline__ void cp16(uint32_t dst, const void* src) {
    asm volatile("cp.async.cg.shared.global [%0], [%1], 16;" :: "r"(dst), "l"(src));
}
#define CP_COMMIT() asm volatile("cp.async.commit_group;" ::: "memory")
#define CP_WAIT(n)  asm volatile("cp.async.wait_group %0;" :: "n"(n) : "memory")

__device__ __forceinline__ void ldm4(uint32_t* r, uint32_t addr) {
    asm volatile("ldmatrix.sync.aligned.m8n8.x4.shared.b16 {%0,%1,%2,%3}, [%4];"
        : "=r"(r[0]), "=r"(r[1]), "=r"(r[2]), "=r"(r[3]) : "r"(addr));
}

// D(f32) += A(bf16,row) * B(bf16,col);  m16n8k16
// Fragment byte-layout identical to s8 m16n8k32 (32B/row per frag) — the
// ldmatrix choreography below is the one empirically validated in R6/R8.
__device__ __forceinline__ void mma_bf16(float* d, const uint32_t* a, uint32_t b0, uint32_t b1) {
    asm volatile(
        "mma.sync.aligned.m16n8k16.row.col.f32.bf16.bf16.f32 "
        "{%0,%1,%2,%3}, {%4,%5,%6,%7}, {%8,%9}, {%0,%1,%2,%3};"
        : "+f"(d[0]), "+f"(d[1]), "+f"(d[2]), "+f"(d[3])
        : "r"(a[0]), "r"(a[1]), "r"(a[2]), "r"(a[3]), "r"(b0), "r"(b1));
}

// ============================================================================
// W convert: int32-stored int8 weights -> bf16 (exact for |w| <= 256).
// Each thread: 8 int32 (32B) -> 8 bf16 (16B).
// ============================================================================
__global__ void __launch_bounds__(256) k_wsplit(const int4* __restrict__ w32) {
    size_t i = (size_t)blockIdx.x * blockDim.x + threadIdx.x;   // 0 .. 8388607
    int4 v0 = w32[i * 2 + 0];
    int4 v1 = w32[i * 2 + 1];
    uint32_t p[4];
    p[0] = (uint32_t)__bfloat16_as_ushort(__float2bfloat16((float)v0.x)) |
           ((uint32_t)__bfloat16_as_ushort(__float2bfloat16((float)v0.y)) << 16);
    p[1] = (uint32_t)__bfloat16_as_ushort(__float2bfloat16((float)v0.z)) |
           ((uint32_t)__bfloat16_as_ushort(__float2bfloat16((float)v0.w)) << 16);
    p[2] = (uint32_t)__bfloat16_as_ushort(__float2bfloat16((float)v1.x)) |
           ((uint32_t)__bfloat16_as_ushort(__float2bfloat16((float)v1.y)) << 16);
    p[3] = (uint32_t)__bfloat16_as_ushort(__float2bfloat16((float)v1.z)) |
           ((uint32_t)__bfloat16_as_ushort(__float2bfloat16((float)v1.w)) << 16);
    *(uint4*)((char*)g_Wb + i * 16) = make_uint4(p[0], p[1], p[2], p[3]);
}

// ============================================================================
// x split: x -> hi = bf16(x), lo = bf16(x - hi).  Pure elementwise.
// Each thread: one float4 -> 4 bf16 hi (8B) + 4 bf16 lo (8B).
// ============================================================================
__global__ void __launch_bounds__(256) k_xsplit(const float4* __restrict__ x) {
    size_t i = (size_t)blockIdx.x * blockDim.x + threadIdx.x;   // 0 .. 8388607
    float4 v = x[i];
    __nv_bfloat16 h0 = __float2bfloat16(v.x), h1 = __float2bfloat16(v.y);
    __nv_bfloat16 h2 = __float2bfloat16(v.z), h3 = __float2bfloat16(v.w);
    __nv_bfloat16 l0 = __float2bfloat16(v.x - __bfloat162float(h0));
    __nv_bfloat16 l1 = __float2bfloat16(v.y - __bfloat162float(h1));
    __nv_bfloat16 l2 = __float2bfloat16(v.z - __bfloat162float(h2));
    __nv_bfloat16 l3 = __float2bfloat16(v.w - __bfloat162float(h3));
    uint2 H, L;
    H.x = (uint32_t)__bfloat16_as_ushort(h0) | ((uint32_t)__bfloat16_as_ushort(h1) << 16);
    H.y = (uint32_t)__bfloat16_as_ushort(h2) | ((uint32_t)__bfloat16_as_ushort(h3) << 16);
    L.x = (uint32_t)__bfloat16_as_ushort(l0) | ((uint32_t)__bfloat16_as_ushort(l1) << 16);
    L.y = (uint32_t)__bfloat16_as_ushort(l2) | ((uint32_t)__bfloat16_as_ushort(l3) << 16);
    *(uint2*)((char*)g_Ahi + i * 8) = H;
    *(uint2*)((char*)g_Alo + i * 8) = L;
}

// ============================================================================
// GEMM: acc(f32) = (Ahi + Alo) @ Wb^T   (both partials into one accumulator)
// out = acc * scale_n + bias_n
// Block 128x128, 16 warps (4m x 4n), warp tile 32x32, 4-stage cp.async.
// ============================================================================
__global__ void __launch_bounds__(NTHREADS, 1) gemm_kernel(
    const float* __restrict__ scale,   // [NN]
    const float* __restrict__ bias,    // [NN]
    float* __restrict__ out)           // [MM][NN]
{
    extern __shared__ char smem[];
    uint32_t sb = smem_to_u32(smem);
    int tid = threadIdx.x;

    // L2-friendly tile order: groups of 8 m-tiles sweep n
    const int ntm = MM / BM, ntn = NN / BN;   // 64, 128
    const int GROUPM = 8;
    int pid = blockIdx.x;
    int npg = GROUPM * ntn;
    int gid = pid / npg;
    int fm = gid * GROUPM;
    int gsz = (ntm - fm < GROUPM) ? (ntm - fm) : GROUPM;
    int tm = fm + (pid % gsz);
    int tn = (pid % npg) / gsz;
    int m0 = tm * BM, n0 = tn * BN;

    const char* pAhi = (const char*)g_Ahi;
    const char* pAlo = (const char*)g_Alo;
    const char* pW   = (const char*)g_Wb;
    const size_t RB = (size_t)KK * 2;        // bytes per logical row

    // ---- stage loader: 1536 x 16B chunks / 512 threads = 3 per thread ----
    auto load_stage = [&](int slot, int kt) {
        uint32_t sbase = sb + slot * STAGE_BYTES;
        size_t k0 = (size_t)kt * BKB;
#pragma unroll
        for (int i = 0; i < 3; i++) {
            int c = tid + i * NTHREADS;      // 0..1535
            int arr = c >> 9;                // 0:Ahi 1:Alo 2:W
            int idx = c & 511;
            int row = idx >> 2, ch = idx & 3;
            uint32_t dst = sbase + arr * ATILE + row * ROWB + ch * 16;
            const char* src;
            if (arr == 0)      src = pAhi + (size_t)(m0 + row) * RB + k0 + ch * 16;
            else if (arr == 1) src = pAlo + (size_t)(m0 + row) * RB + k0 + ch * 16;
            else               src = pW   + (size_t)(n0 + row) * RB + k0 + ch * 16;
            cp16(dst, src);
        }
    };

    int w = tid >> 5, lane = tid & 31;
    int mw = w >> 2, nw = w & 3;             // warp grid 4m x 4n, warp tile 32x32
    int r = lane & 7, seg = lane >> 3;
    int g = lane >> 2, q = lane & 3;         // C-fragment coords

    // ldmatrix source offsets — validated choreography (R6/R8), byte-identical
    uint32_t aoff[2];
#pragma unroll
    for (int mf = 0; mf < 2; mf++) {
        int arow = mw * 32 + mf * 16 + r + (seg & 1) * 8;
        aoff[mf] = (uint32_t)arow * ROWB + (seg >> 1) * 16;
    }
    uint32_t boff[2];
#pragma unroll
    for (int p = 0; p < 2; p++) {
        int brow = nw * 32 + p * 16 + r + (seg >> 1) * 8;
        boff[p] = 2 * ATILE + (uint32_t)brow * ROWB + (seg & 1) * 16;
    }

    float acc[2][4][4] = {};   // [m16 frag][n8 frag][c0..c3]  hi+lo merged

    // ---- prologue ----
#pragma unroll
    for (int s = 0; s < STAGES - 1; s++) { load_stage(s, s); CP_COMMIT(); }

    // ---- mainloop ----
    for (int kt = 0; kt < KTILES; kt++) {
        CP_WAIT(STAGES - 2);
        __syncthreads();
        if (kt + STAGES - 1 < KTILES) load_stage((kt + STAGES - 1) % STAGES, kt + STAGES - 1);
        CP_COMMIT();

        uint32_t sbase = sb + (kt % STAGES) * STAGE_BYTES;
#pragma unroll
        for (int ks = 0; ks < 2; ks++) {     // 2 x 32B = 2 x k16 per tile
            uint32_t fa[2][4], fb[2][4], fB[2][4];
#pragma unroll
            for (int mf = 0; mf < 2; mf++) {
                ldm4(fa[mf], sbase + aoff[mf] + ks * 32);
                ldm4(fb[mf], sbase + ATILE + aoff[mf] + ks * 32);
            }
#pragma unroll
            for (int p = 0; p < 2; p++) ldm4(fB[p], sbase + boff[p] + ks * 32);
#pragma unroll
            for (int mf = 0; mf < 2; mf++) {
#pragma unroll
                for (int nf = 0; nf < 4; nf++) {
                    uint32_t b0 = fB[nf >> 1][(nf & 1) * 2];
                    uint32_t b1 = fB[nf >> 1][(nf & 1) * 2 + 1];
                    mma_bf16(acc[mf][nf], fa[mf], b0, b1);   // hi partial
                    mma_bf16(acc[mf][nf], fb[mf], b0, b1);   // lo partial
                }
            }
        }
    }

    // ---- epilogue: out = acc * scale_n + bias_n ----
    // C frag: c0:(g, 2q) c1:(g, 2q+1) c2:(g+8, 2q) c3:(g+8, 2q+1)
#pragma unroll
    for (int mf = 0; mf < 2; mf++) {
        int r0 = m0 + mw * 32 + mf * 16 + g;
#pragma unroll
        for (int nf = 0; nf < 4; nf++) {
            int c = n0 + nw * 32 + nf * 8 + q * 2;
            float sc0 = __ldg(scale + c), sc1 = __ldg(scale + c + 1);
            float bb0 = __ldg(bias + c),  bb1 = __ldg(bias + c + 1);
            const float* d = acc[mf][nf];
            float2 v0 = make_float2(fmaf(d[0], sc0, bb0), fmaf(d[1], sc1, bb1));
            float2 v1 = make_float2(fmaf(d[2], sc0, bb0), fmaf(d[3], sc1, bb1));
            *(float2*)(out + (size_t)r0 * NN + c)       = v0;
            *(float2*)(out + (size_t)(r0 + 8) * NN + c) = v1;
        }
    }
}

// ============================================================================
// Host side — inputs identified by element count
// ============================================================================
extern "C" void kernel_launch(void* const* d_in, const int* in_sizes, int n_in,
                              void* d_out, int out_size) {
    const float*   x     = nullptr;
    const int32_t* w32   = nullptr;
    const float*   scale = nullptr;
    const float*   bias  = nullptr;
    for (int i = 0; i < n_in; i++) {
        if (in_sizes[i] == MM * KK)           x   = (const float*)d_in[i];
        else if (in_sizes[i] == NN * KK)      w32 = (const int32_t*)d_in[i];
        else if (in_sizes[i] == NN) {
            if (!scale) scale = (const float*)d_in[i];
            else        bias  = (const float*)d_in[i];
        }
    }
    float* out = (float*)d_out;

    cudaFuncSetAttribute(gemm_kernel, cudaFuncAttributeMaxDynamicSharedMemorySize, SMEM_BYTES);

    k_wsplit<<<(NN * (size_t)KK) / (8 * 256), 256>>>((const int4*)w32);
    k_xsplit<<<(MM * (size_t)KK) / (4 * 256), 256>>>((const float4*)x);
    gemm_kernel<<<(MM / BM) * (NN / BN), NTHREADS, SMEM_BYTES>>>(scale, bias, out);
}

// round 11
// speedup vs baseline: 4.2330x; 1.6560x over previous
#include <cuda_runtime.h>
#include <cuda_fp16.h>
#include <cstdint>

// ============================================================================
// Problem sizes / tiling
// ============================================================================
#define MM 8192
#define NN 16384
#define KK 4096
#define BM 128
#define BN 128
#define BKB 64                  // K-bytes per stage tile = 32 fp16 elements
#define STAGES 4
#define KTILES (KK * 2 / BKB)   // 128
#define ROWB 80                 // padded SMEM row: 64 data bytes + 16 pad (conflict-free)
#define ATILE (BM * ROWB)       // 10240 bytes per tile array
#define STAGE_BYTES (2 * ATILE) // A + W tiles = 20480
#define SMEM_BYTES (STAGES * STAGE_BYTES)  // 81920
#define NTHREADS 512

// Scratch (allocation-free rule: __device__ globals)
static __device__ __align__(1024) __half g_A[(size_t)MM * KK];   // 64 MB  fp16 x
static __device__ __align__(1024) __half g_Wh[(size_t)NN * KK];  // 128 MB fp16 weights

// ============================================================================
// PTX helpers (plain sm_103-safe)
// ============================================================================
__device__ __forceinline__ uint32_t smem_to_u32(const void* p) {
    uint32_t a;
    asm("{ .reg .u64 t; cvta.to.shared.u64 t, %1; cvt.u32.u64 %0, t; }" : "=r"(a) : "l"(p));
    return a;
}

__device__ __forceinline__ void cp16(uint32_t dst, const void* src) {
    asm volatile("cp.async.cg.shared.global [%0], [%1], 16;" :: "r"(dst), "l"(src));
}
#define CP_COMMIT() asm volatile("cp.async.commit_group;" ::: "memory")
#define CP_WAIT(n)  asm volatile("cp.async.wait_group %0;" :: "n"(n) : "memory")

__device__ __forceinline__ void ldm4(uint32_t* r, uint32_t addr) {
    asm volatile("ldmatrix.sync.aligned.m8n8.x4.shared.b16 {%0,%1,%2,%3}, [%4];"
        : "=r"(r[0]), "=r"(r[1]), "=r"(r[2]), "=r"(r[3]) : "r"(addr));
}

// D(f32) += A(f16,row) * B(f16,col);  m16n8k16
// Fragment byte-layout identical to the validated bf16/s8 choreography.
__device__ __forceinline__ void mma_f16(float* d, const uint32_t* a, uint32_t b0, uint32_t b1) {
    asm volatile(
        "mma.sync.aligned.m16n8k16.row.col.f32.f16.f16.f32 "
        "{%0,%1,%2,%3}, {%4,%5,%6,%7}, {%8,%9}, {%0,%1,%2,%3};"
        : "+f"(d[0]), "+f"(d[1]), "+f"(d[2]), "+f"(d[3])
        : "r"(a[0]), "r"(a[1]), "r"(a[2]), "r"(a[3]), "r"(b0), "r"(b1));
}

// ============================================================================
// W convert: int32-stored int8 weights -> fp16 (exact for |w| <= 2048).
// Each thread: 8 int32 (32B) -> 8 fp16 (16B).
// ============================================================================
__global__ void __launch_bounds__(256) k_wconv(const int4* __restrict__ w32) {
    size_t i = (size_t)blockIdx.x * blockDim.x + threadIdx.x;   // 0 .. 8388607
    int4 v0 = w32[i * 2 + 0];
    int4 v1 = w32[i * 2 + 1];
    uint32_t p[4];
    p[0] = (uint32_t)__half_as_ushort(__float2half_rn((float)v0.x)) |
           ((uint32_t)__half_as_ushort(__float2half_rn((float)v0.y)) << 16);
    p[1] = (uint32_t)__half_as_ushort(__float2half_rn((float)v0.z)) |
           ((uint32_t)__half_as_ushort(__float2half_rn((float)v0.w)) << 16);
    p[2] = (uint32_t)__half_as_ushort(__float2half_rn((float)v1.x)) |
           ((uint32_t)__half_as_ushort(__float2half_rn((float)v1.y)) << 16);
    p[3] = (uint32_t)__half_as_ushort(__float2half_rn((float)v1.z)) |
           ((uint32_t)__half_as_ushort(__float2half_rn((float)v1.w)) << 16);
    *(uint4*)((char*)g_Wh + i * 16) = make_uint4(p[0], p[1], p[2], p[3]);
}

// ============================================================================
// x convert: f32 -> fp16 (rel rounding RMS ~3e-4, within 1e-3 budget).
// Each thread: one float4 -> 4 fp16 (8B).
// ============================================================================
__global__ void __launch_bounds__(256) k_xconv(const float4* __restrict__ x) {
    size_t i = (size_t)blockIdx.x * blockDim.x + threadIdx.x;   // 0 .. 8388607
    float4 v = x[i];
    uint2 H;
    H.x = (uint32_t)__half_as_ushort(__float2half_rn(v.x)) |
          ((uint32_t)__half_as_ushort(__float2half_rn(v.y)) << 16);
    H.y = (uint32_t)__half_as_ushort(__float2half_rn(v.z)) |
          ((uint32_t)__half_as_ushort(__float2half_rn(v.w)) << 16);
    *(uint2*)((char*)g_A + i * 8) = H;
}

// ============================================================================
// GEMM: acc(f32) = A @ Wh^T ;  out = acc * scale_n + bias_n
// Block 128x128, 16 warps (4m x 4n), warp tile 32x32, 4-stage cp.async.
// ============================================================================
__global__ void __launch_bounds__(NTHREADS, 1) gemm_kernel(
    const float* __restrict__ scale,   // [NN]
    const float* __restrict__ bias,    // [NN]
    float* __restrict__ out)           // [MM][NN]
{
    extern __shared__ char smem[];
    uint32_t sb = smem_to_u32(smem);
    int tid = threadIdx.x;

    // L2-friendly tile order: groups of 8 m-tiles sweep n
    const int ntm = MM / BM, ntn = NN / BN;   // 64, 128
    const int GROUPM = 8;
    int pid = blockIdx.x;
    int npg = GROUPM * ntn;
    int gid = pid / npg;
    int fm = gid * GROUPM;
    int gsz = (ntm - fm < GROUPM) ? (ntm - fm) : GROUPM;
    int tm = fm + (pid % gsz);
    int tn = (pid % npg) / gsz;
    int m0 = tm * BM, n0 = tn * BN;

    const char* pA = (const char*)g_A;
    const char* pW = (const char*)g_Wh;
    const size_t RB = (size_t)KK * 2;        // bytes per logical row

    // ---- stage loader: 1024 x 16B chunks / 512 threads = 2 per thread ----
    auto load_stage = [&](int slot, int kt) {
        uint32_t sbase = sb + slot * STAGE_BYTES;
        size_t k0 = (size_t)kt * BKB;
#pragma unroll
        for (int i = 0; i < 2; i++) {
            int c = tid + i * NTHREADS;      // 0..1023
            int arr = c >> 9;                // 0:A 1:W
            int idx = c & 511;
            int row = idx >> 2, ch = idx & 3;
            uint32_t dst = sbase + arr * ATILE + row * ROWB + ch * 16;
            const char* src = (arr == 0)
                ? pA + (size_t)(m0 + row) * RB + k0 + ch * 16
                : pW + (size_t)(n0 + row) * RB + k0 + ch * 16;
            cp16(dst, src);
        }
    };

    int w = tid >> 5, lane = tid & 31;
    int mw = w >> 2, nw = w & 3;             // warp grid 4m x 4n, warp tile 32x32
    int r = lane & 7, seg = lane >> 3;
    int g = lane >> 2, q = lane & 3;         // C-fragment coords

    // ldmatrix source offsets — validated choreography (R6/R8/R10)
    uint32_t aoff[2];
#pragma unroll
    for (int mf = 0; mf < 2; mf++) {
        int arow = mw * 32 + mf * 16 + r + (seg & 1) * 8;
        aoff[mf] = (uint32_t)arow * ROWB + (seg >> 1) * 16;
    }
    uint32_t boff[2];
#pragma unroll
    for (int p = 0; p < 2; p++) {
        int brow = nw * 32 + p * 16 + r + (seg >> 1) * 8;
        boff[p] = ATILE + (uint32_t)brow * ROWB + (seg & 1) * 16;
    }

    float acc[2][4][4] = {};   // [m16 frag][n8 frag][c0..c3]

    // ---- prologue ----
#pragma unroll
    for (int s = 0; s < STAGES - 1; s++) { load_stage(s, s); CP_COMMIT(); }

    // ---- mainloop ----
    for (int kt = 0; kt < KTILES; kt++) {
        CP_WAIT(STAGES - 2);
        __syncthreads();
        if (kt + STAGES - 1 < KTILES) load_stage((kt + STAGES - 1) % STAGES, kt + STAGES - 1);
        CP_COMMIT();

        uint32_t sbase = sb + (kt % STAGES) * STAGE_BYTES;
#pragma unroll
        for (int ks = 0; ks < 2; ks++) {     // 2 x 32B = 2 x k16 per tile
            uint32_t fa[2][4], fB[2][4];
#pragma unroll
            for (int mf = 0; mf < 2; mf++) ldm4(fa[mf], sbase + aoff[mf] + ks * 32);
#pragma unroll
            for (int p = 0; p < 2; p++)    ldm4(fB[p], sbase + boff[p] + ks * 32);
#pragma unroll
            for (int mf = 0; mf < 2; mf++) {
#pragma unroll
                for (int nf = 0; nf < 4; nf++) {
                    uint32_t b0 = fB[nf >> 1][(nf & 1) * 2];
                    uint32_t b1 = fB[nf >> 1][(nf & 1) * 2 + 1];
                    mma_f16(acc[mf][nf], fa[mf], b0, b1);
                }
            }
        }
    }

    // ---- epilogue: out = acc * scale_n + bias_n ----
    // C frag: c0:(g, 2q) c1:(g, 2q+1) c2:(g+8, 2q) c3:(g+8, 2q+1)
#pragma unroll
    for (int mf = 0; mf < 2; mf++) {
        int r0 = m0 + mw * 32 + mf * 16 + g;
#pragma unroll
        for (int nf = 0; nf < 4; nf++) {
            int c = n0 + nw * 32 + nf * 8 + q * 2;
            float sc0 = __ldg(scale + c), sc1 = __ldg(scale + c + 1);
            float bb0 = __ldg(bias + c),  bb1 = __ldg(bias + c + 1);
            const float* d = acc[mf][nf];
            float2 v0 = make_float2(fmaf(d[0], sc0, bb0), fmaf(d[1], sc1, bb1));
            float2 v1 = make_float2(fmaf(d[2], sc0, bb0), fmaf(d[3], sc1, bb1));
            *(float2*)(out + (size_t)r0 * NN + c)       = v0;
            *(float2*)(out + (size_t)(r0 + 8) * NN + c) = v1;
        }
    }
}

// ============================================================================
// Host side — inputs identified by element count
// ============================================================================
extern "C" void kernel_launch(void* const* d_in, const int* in_sizes, int n_in,
                              void* d_out, int out_size) {
    const float*   x     = nullptr;
    const int32_t* w32   = nullptr;
    const float*   scale = nullptr;
    const float*   bias  = nullptr;
    for (int i = 0; i < n_in; i++) {
        if (in_sizes[i] == MM * KK)           x   = (const float*)d_in[i];
        else if (in_sizes[i] == NN * KK)      w32 = (const int32_t*)d_in[i];
        else if (in_sizes[i] == NN) {
            if (!scale) scale = (const float*)d_in[i];
            else        bias  = (const float*)d_in[i];
        }
    }
    float* out = (float*)d_out;

    cudaFuncSetAttribute(gemm_kernel, cudaFuncAttributeMaxDynamicSharedMemorySize, SMEM_BYTES);

    k_wconv<<<(NN * (size_t)KK) / (8 * 256), 256>>>((const int4*)w32);
    k_xconv<<<(MM * (size_t)KK) / (4 * 256), 256>>>((const float4*)x);
    gemm_kernel<<<(MM / BM) * (NN / BN), NTHREADS, SMEM_BYTES>>>(scale, bias, out);
}